// round 11
// baseline (speedup 1.0000x reference)
#include <cuda_runtime.h>
#include <math.h>
#include <stdint.h>

#define N 8192
#define NTRI 2730
#define NEDGE 2048
#define HID 256
#define DK 128
#define CAP 64
#define EPSF 1.1920928955078125e-07f

// GEMM tiling
#define BM 64
#define HSTR 260
#define BSTR 264

// ---------------- scratch (device globals; zero-initialized at load) --------
__device__ float g_M[16];
__device__ float g_C[4 * HID];
__device__ float g_D[5 * HID];        // rows 0-3: D=(C*g1)@W1 ; row 4: d=(b0*g1)@W1
__device__ uint32_t g_Wt[HID * HID];  // tf32(g2 * W2)
__device__ int g_cnt[NTRI];           // zeroed by k_norm for next replay
__device__ float g_esum[NEDGE];       // zeroed by k_fill each call
__device__ float g_eexp[N];
__device__ float4 g_tri_feat[NTRI * CAP];

__device__ __forceinline__ uint32_t f2tf32(float x) {
    uint32_t r;
    asm("cvt.rna.tf32.f32 %0, %1;" : "=r"(r) : "f"(x));
    return r;
}

// ---------------- ALL weight preprocessing in ONE block (side stream) --------
// phase A: M (4x4), C (4x256); phase B: D (5x256); phase C: Wt = tf32(g2*W2)
__global__ void __launch_bounds__(1024, 1)
k_init(const float* __restrict__ Wq, const float* __restrict__ bq,
       const float* __restrict__ Wk, const float* __restrict__ bk,
       const float* __restrict__ Wv, const float* __restrict__ bv,
       const float* __restrict__ W0, const float* __restrict__ b0,
       const float* __restrict__ rmsw, const float* __restrict__ Wres) {
    int tid = threadIdx.x;  // 1024
    // --- A: M and C ---
    if (tid < 16) {
        int r = tid >> 2, s = tid & 3;
        const float* qa = (r < 3) ? (Wq + r * DK) : bq;
        const float* ka = (s < 3) ? (Wk + s * DK) : bk;
        float acc = 0.f;
        for (int k = 0; k < DK; k++) acc = fmaf(qa[k], ka[k], acc);
        g_M[tid] = acc * 0.08838834764831845f;  // 1/sqrt(128)
    }
    {
        int r = tid >> 8, o = tid & 255;
        const float* va = (r < 3) ? (Wv + r * DK) : bv;
        float acc = 0.f;
        for (int k = 0; k < DK; k++) acc = fmaf(va[k], W0[k * HID + o], acc);
        g_C[tid] = acc;
    }
    __syncthreads();
    // --- B: D = (C*g1)@W1, d = (b0*g1)@W1 ---
    const float* g1 = rmsw;               // row 0
    const float* W1 = Wres;               // block 0
    for (int gid = tid; gid < 5 * HID; gid += 1024) {
        int r = gid >> 8, o = gid & 255;
        float acc = 0.f;
        if (r < 4) {
            const float* cr = g_C + r * HID;
            for (int j = 0; j < HID; j++) acc = fmaf(cr[j] * g1[j], W1[j * HID + o], acc);
        } else {
            for (int j = 0; j < HID; j++) acc = fmaf(b0[j] * g1[j], W1[j * HID + o], acc);
        }
        g_D[gid] = acc;
    }
    // --- C: Wt = tf32(g2 ∘ W2) ---
    const float* g2 = rmsw + HID;
    const float* W2 = Wres + HID * HID;
#pragma unroll
    for (int it = 0; it < 16; it++) {
        int i = tid + it * 1024;           // [0, HID*HID/4)
        int k = i >> 6;
        float4 w = ((const float4*)W2)[i];
        float gk = g2[k];
        uint4 o;
        o.x = f2tf32(w.x * gk); o.y = f2tf32(w.y * gk);
        o.z = f2tf32(w.z * gk); o.w = f2tf32(w.w * gk);
        ((uint4*)g_Wt)[i] = o;
    }
}

// ---------------- bucket fill + esum zeroing ---------------------------------
__global__ void k_fill(const float* __restrict__ ef, const int* __restrict__ tri) {
    int i = blockIdx.x * 128 + threadIdx.x;   // grid 64 x 128 = 8192
    if (i < NEDGE) g_esum[i] = 0.f;
    if (i >= N) return;
    float x0 = ef[3 * i], x1 = ef[3 * i + 1], x2 = ef[3 * i + 2];
    int t = tri[i];
    int slot = atomicAdd(&g_cnt[t], 1);
    if (slot < CAP)
        g_tri_feat[t * CAP + slot] = make_float4(x0, x1, x2, 0.f);
}

// ---- fused attention + h1-build + tf32 resblock2 GEMM + exp + edge-sum ------
__global__ void __launch_bounds__(256, 1)
k_gemm(const float* __restrict__ ef, const int* __restrict__ tri,
       const int* __restrict__ eid,
       const float* __restrict__ b0, const float* __restrict__ b1,
       const float* __restrict__ b2, const float* __restrict__ Wout,
       const float* __restrict__ bout) {
    extern __shared__ float sm[];
    float* sH = sm;                                    // [BM][HSTR] h1 fp32
    uint32_t* sB = (uint32_t*)(sm + BM * HSTR);        // [32][BSTR] tf32
    float* sWout = (float*)(sB + 32 * BSTR);           // [HID]
    float* sBres = sWout + HID;                        // [HID]
    float* sRS = sBres + HID;                          // [BM]
    float* sRed = sRS + BM;                            // [BM*4]
    float4* sYa = (float4*)(sRed + BM * 4);            // [BM]

    int tid = threadIdx.x, lane = tid & 31, wid = tid >> 5;
    int row0 = blockIdx.x * BM;

    if (tid < HID) { sWout[tid] = Wout[tid]; sBres[tid] = b2[tid]; }

    // ---------- attention for this block's 64 nodes (tid < 64) ----------
    if (tid < BM) {
        int node = row0 + tid;
        float x0 = ef[3 * node], x1 = ef[3 * node + 1], x2 = ef[3 * node + 2];
        float u0 = x0 * g_M[0] + x1 * g_M[4] + x2 * g_M[8]  + g_M[12];
        float u1 = x0 * g_M[1] + x1 * g_M[5] + x2 * g_M[9]  + g_M[13];
        float u2 = x0 * g_M[2] + x1 * g_M[6] + x2 * g_M[10] + g_M[14];
        float u3 = x0 * g_M[3] + x1 * g_M[7] + x2 * g_M[11] + g_M[15];
        int t = tri[node];
        int cnt = g_cnt[t];
        if (cnt > CAP) cnt = CAP;
        const float4* base = g_tri_feat + t * CAP;
        float sum = 0.f, y0 = 0.f, y1 = 0.f, y2 = 0.f;
#pragma unroll 4
        for (int j = 0; j < cnt; j++) {
            float4 f = base[j];
            float s = fmaf(u0, f.x, fmaf(u1, f.y, fmaf(u2, f.z, u3)));
            float w = __expf(s);     // |s| << 1: no max-shift needed
            sum += w;
            y0 = fmaf(w, f.x, y0); y1 = fmaf(w, f.y, y1); y2 = fmaf(w, f.z, y2);
        }
        float inv = 1.f / sum;
        sYa[tid] = make_float4(y0 * inv, y1 * inv, y2 * inv, 1.f);
    }
    __syncthreads();

    // ---------- prologue: each warp builds 8 rows of h1 ----------
    {
        int rbase = wid * 8;
        float4 ya[8];
#pragma unroll
        for (int m = 0; m < 8; m++) ya[m] = sYa[rbase + m];
        float sqr[8];
#pragma unroll
        for (int m = 0; m < 8; m++) sqr[m] = 0.f;
#pragma unroll
        for (int t = 0; t < 8; t++) {
            int c = lane + 32 * t;
            float C0 = g_C[c], C1 = g_C[256 + c], C2 = g_C[512 + c], C3 = g_C[768 + c];
            float bb = b0[c];
#pragma unroll
            for (int m = 0; m < 8; m++) {
                float v = bb;
                v = fmaf(ya[m].x, C0, v); v = fmaf(ya[m].y, C1, v);
                v = fmaf(ya[m].z, C2, v); v = fmaf(ya[m].w, C3, v);
                sH[(rbase + m) * HSTR + c] = v;
                sqr[m] = fmaf(v, v, sqr[m]);
            }
        }
        float rsr[8];
#pragma unroll
        for (int m = 0; m < 8; m++) {
            float s = sqr[m];
#pragma unroll
            for (int o = 16; o; o >>= 1) s += __shfl_xor_sync(0xffffffffu, s, o);
            rsr[m] = rsqrtf(s * (1.0f / 256.0f) + EPSF);
        }
        float sq2[8];
#pragma unroll
        for (int m = 0; m < 8; m++) sq2[m] = 0.f;
#pragma unroll
        for (int t = 0; t < 8; t++) {
            int c = lane + 32 * t;
            float D0 = g_D[c], D1 = g_D[256 + c], D2 = g_D[512 + c], D3 = g_D[768 + c];
            float D4 = g_D[1024 + c];
            float b1c = b1[c];
#pragma unroll
            for (int m = 0; m < 8; m++) {
                float z = D4;
                z = fmaf(ya[m].x, D0, z); z = fmaf(ya[m].y, D1, z);
                z = fmaf(ya[m].z, D2, z); z = fmaf(ya[m].w, D3, z);
                z = fmaf(rsr[m], z, b1c);
                float h0v = sH[(rbase + m) * HSTR + c];
                float h1v = h0v + fmaxf(z, 0.f);
                sH[(rbase + m) * HSTR + c] = h1v;
                sq2[m] = fmaf(h1v, h1v, sq2[m]);
            }
        }
#pragma unroll
        for (int m = 0; m < 8; m++) {
            float s = sq2[m];
#pragma unroll
            for (int o = 16; o; o >>= 1) s += __shfl_xor_sync(0xffffffffu, s, o);
            if (lane == 0) sRS[rbase + m] = rsqrtf(s * (1.0f / 256.0f) + EPSF);
        }
    }
    __syncthreads();

    // ---------- tf32 mma mainloop (B pre-converted in g_Wt) ----------
    int wm = wid >> 2, wn = wid & 3;
    int lg = lane >> 2, lq = lane & 3;
    float rsv[4];
#pragma unroll
    for (int q = 0; q < 4; q++) rsv[q] = sRS[wm * 32 + q * 8 + lg];

    float acc[2][8][4];
#pragma unroll
    for (int mt = 0; mt < 2; mt++)
#pragma unroll
        for (int nt = 0; nt < 8; nt++)
#pragma unroll
            for (int q = 0; q < 4; q++) acc[mt][nt][q] = 0.f;

    for (int kk = 0; kk < HID; kk += 32) {
#pragma unroll
        for (int it = 0; it < 8; it++) {
            int i = tid + it * 256;
            int k = i >> 6, c4 = i & 63;
            uint4 w = ((const uint4*)(g_Wt + (kk + k) * HID))[c4];
            uint32_t* d = &sB[k * BSTR + c4 * 4];
            d[0] = w.x; d[1] = w.y; d[2] = w.z; d[3] = w.w;
        }
        __syncthreads();

#pragma unroll
        for (int ks = 0; ks < 4; ks++) {
            int col = kk + ks * 8 + lq;
            uint32_t a[2][4];
#pragma unroll
            for (int mt = 0; mt < 2; mt++) {
                int r = wm * 32 + mt * 16 + lg;
                a[mt][0] = f2tf32(sH[r * HSTR + col] * rsv[mt * 2]);
                a[mt][1] = f2tf32(sH[(r + 8) * HSTR + col] * rsv[mt * 2 + 1]);
                a[mt][2] = f2tf32(sH[r * HSTR + col + 4] * rsv[mt * 2]);
                a[mt][3] = f2tf32(sH[(r + 8) * HSTR + col + 4] * rsv[mt * 2 + 1]);
            }
            int k0 = ks * 8;
            uint32_t b[8][2];
#pragma unroll
            for (int nt = 0; nt < 8; nt++) {
                int c = wn * 64 + nt * 8 + lg;
                b[nt][0] = sB[(k0 + lq) * BSTR + c];
                b[nt][1] = sB[(k0 + lq + 4) * BSTR + c];
            }
#pragma unroll
            for (int mt = 0; mt < 2; mt++)
#pragma unroll
                for (int nt = 0; nt < 8; nt++) {
                    asm volatile(
                        "mma.sync.aligned.m16n8k8.row.col.f32.tf32.tf32.f32 "
                        "{%0,%1,%2,%3}, {%4,%5,%6,%7}, {%8,%9}, {%0,%1,%2,%3};"
                        : "+f"(acc[mt][nt][0]), "+f"(acc[mt][nt][1]),
                          "+f"(acc[mt][nt][2]), "+f"(acc[mt][nt][3])
                        : "r"(a[mt][0]), "r"(a[mt][1]), "r"(a[mt][2]), "r"(a[mt][3]),
                          "r"(b[nt][0]), "r"(b[nt][1]));
                }
        }
        __syncthreads();
    }

    // ---------- epilogue: residual + relu + Wout dot ----------
#pragma unroll
    for (int mt = 0; mt < 2; mt++) {
        int i0 = wm * 32 + mt * 16 + lg;
        int i1 = i0 + 8;
        float plo = 0.f, phi = 0.f;
#pragma unroll
        for (int nt = 0; nt < 8; nt++) {
            int j0 = wn * 64 + nt * 8 + lq * 2;
            float w0 = sWout[j0], w1 = sWout[j0 + 1];
            float br0 = sBres[j0], br1 = sBres[j0 + 1];
            float h00 = sH[i0 * HSTR + j0], h01 = sH[i0 * HSTR + j0 + 1];
            float h10 = sH[i1 * HSTR + j0], h11 = sH[i1 * HSTR + j0 + 1];
            plo = fmaf(h00 + fmaxf(acc[mt][nt][0] + br0, 0.f), w0, plo);
            plo = fmaf(h01 + fmaxf(acc[mt][nt][1] + br1, 0.f), w1, plo);
            phi = fmaf(h10 + fmaxf(acc[mt][nt][2] + br0, 0.f), w0, phi);
            phi = fmaf(h11 + fmaxf(acc[mt][nt][3] + br1, 0.f), w1, phi);
        }
        plo += __shfl_xor_sync(0xffffffffu, plo, 1);
        plo += __shfl_xor_sync(0xffffffffu, plo, 2);
        phi += __shfl_xor_sync(0xffffffffu, phi, 1);
        phi += __shfl_xor_sync(0xffffffffu, phi, 2);
        if (lq == 0) {
            sRed[i0 * 4 + wn] = plo;
            sRed[i1 * 4 + wn] = phi;
        }
    }
    __syncthreads();
    // logits are tiny (|l| << 1): exp without max-shift is safe.
    if (tid < BM) {
        float v = sRed[tid * 4] + sRed[tid * 4 + 1] + sRed[tid * 4 + 2] + sRed[tid * 4 + 3];
        float ev = __expf(v + bout[0]);
        int node = row0 + tid;
        g_eexp[node] = ev;
        atomicAdd(&g_esum[eid[node]], ev);
    }
}

// ------ normalize + self-clean g_cnt for next graph replay -------------------
__global__ void k_norm(const int* __restrict__ eid, float* __restrict__ out) {
    int i = blockIdx.x * 256 + threadIdx.x;
    if (i < NTRI) g_cnt[i] = 0;               // reset for next call (last read in k_gemm)
    if (i >= N) return;
    out[i] = g_eexp[i] / g_esum[eid[i]];
}

// ---------------- launcher ---------------------------------------------------
extern "C" void kernel_launch(void* const* d_in, const int* in_sizes, int n_in,
                              void* d_out, int out_size) {
    const float* ef   = (const float*)d_in[0];
    const int*   eid  = (const int*)d_in[1];
    const int*   tri  = (const int*)d_in[2];
    const float* Wq   = (const float*)d_in[3];
    const float* bq   = (const float*)d_in[4];
    const float* Wk   = (const float*)d_in[5];
    const float* bk   = (const float*)d_in[6];
    const float* Wv   = (const float*)d_in[7];
    const float* bv   = (const float*)d_in[8];
    const float* W0   = (const float*)d_in[9];
    const float* b0   = (const float*)d_in[10];
    const float* rmsw = (const float*)d_in[11];
    const float* Wres = (const float*)d_in[12];
    const float* bres = (const float*)d_in[13];
    const float* Wout = (const float*)d_in[14];
    const float* bout = (const float*)d_in[15];
    float* out = (float*)d_out;

    const size_t smem = (BM * HSTR + 32 * BSTR + 2 * HID + BM + BM * 4 + BM * 4) * sizeof(float);

    // lazy one-time setup (runs on the uncaptured correctness call)
    static cudaStream_t s2 = nullptr;
    static cudaEvent_t eFork = nullptr, eInit = nullptr;
    static bool ready = false;
    if (!ready) {
        cudaStreamCreateWithFlags(&s2, cudaStreamNonBlocking);
        cudaEventCreateWithFlags(&eFork, cudaEventDisableTiming);
        cudaEventCreateWithFlags(&eInit, cudaEventDisableTiming);
        cudaFuncSetAttribute(k_gemm, cudaFuncAttributeMaxDynamicSharedMemorySize, (int)smem);
        ready = true;
    }

    // fork side stream off the main (capture) stream
    cudaEventRecord(eFork, 0);
    cudaStreamWaitEvent(s2, eFork, 0);

    // side stream: all weight preprocessing in one kernel
    k_init<<<1, 1024, 0, s2>>>(Wq, bq, Wk, bk, Wv, bv, W0, b0, rmsw, Wres);
    cudaEventRecord(eInit, s2);

    // main stream: fill -> gemm -> norm
    k_fill<<<64, 128>>>(ef, tri);
    cudaStreamWaitEvent(0, eInit, 0);         // gemm needs g_M, g_C, g_D, g_Wt
    k_gemm<<<N / BM, 256, smem>>>(ef, tri, eid, b0, bres, bres + HID, Wout, bout);
    k_norm<<<N / 256, 256>>>(eid, out);
}

// round 13
// speedup vs baseline: 1.2555x; 1.2555x over previous
#include <cuda_runtime.h>
#include <math.h>
#include <stdint.h>

#define N 8192
#define NTRI 2730
#define NEDGE 2048
#define HID 256
#define DK 128
#define CAP 64
#define EPSF 1.1920928955078125e-07f

// GEMM tiling
#define BM 64
#define HSTR 260
#define BSTR 264

// ---------------- scratch (device globals) ----------------------------------
__device__ float g_M[16];
__device__ float g_C[4 * HID];
__device__ float g_D[5 * HID];        // rows 0-3: D=(C*g1)@W1 ; row 4: d=(b0*g1)@W1
__device__ uint32_t g_Wt[HID * HID];  // tf32(g2 * W2)
__device__ int g_cntsum[NTRI + NEDGE]; // [0,NTRI): tri counts (int); [NTRI,..): esum (float bits)
__device__ float g_eexp[N];
__device__ float4 g_tri_feat[NTRI * CAP];

__device__ __forceinline__ uint32_t f2tf32(float x) {
    uint32_t r;
    asm("cvt.rna.tf32.f32 %0, %1;" : "=r"(r) : "f"(x));
    return r;
}

// ---------------- M (4x4) and C (4x256) — one block, side stream ------------
__global__ void __launch_bounds__(1024, 1)
k_initMC(const float* __restrict__ Wq, const float* __restrict__ bq,
         const float* __restrict__ Wk, const float* __restrict__ bk,
         const float* __restrict__ Wv, const float* __restrict__ bv,
         const float* __restrict__ W0) {
    int tid = threadIdx.x;  // 1024
    if (tid < 16) {
        int r = tid >> 2, s = tid & 3;
        const float* qa = (r < 3) ? (Wq + r * DK) : bq;
        const float* ka = (s < 3) ? (Wk + s * DK) : bk;
        float acc = 0.f;
        for (int k = 0; k < DK; k++) acc = fmaf(qa[k], ka[k], acc);
        g_M[tid] = acc * 0.08838834764831845f;  // 1/sqrt(128)
    }
    int r = tid >> 8, o = tid & 255;
    const float* va = (r < 3) ? (Wv + r * DK) : bv;
    float acc = 0.f;
    for (int k = 0; k < DK; k++) acc = fmaf(va[k], W0[k * HID + o], acc);
    g_C[tid] = acc;
}

// ------- D = (C*g1)@W1, d = (b0*g1)@W1  AND  Wt = tf32(g2∘W2), 69 blocks -----
__global__ void k_initDW(const float* __restrict__ rmsw, const float* __restrict__ Wres,
                         const float* __restrict__ b0) {
    int b = blockIdx.x, tid = threadIdx.x;  // 256 threads
    if (b < 5) {
        int gid = b * 256 + tid;            // [0, 5*HID)
        int r = gid >> 8, o = gid & 255;
        const float* g1 = rmsw;
        const float* W1 = Wres;
        float acc = 0.f;
        if (r < 4) {
            const float* cr = g_C + r * HID;
            for (int j = 0; j < HID; j++) acc = fmaf(cr[j] * g1[j], W1[j * HID + o], acc);
        } else {
            for (int j = 0; j < HID; j++) acc = fmaf(b0[j] * g1[j], W1[j * HID + o], acc);
        }
        g_D[gid] = acc;
    } else {
        int i = (b - 5) * 256 + tid;        // [0, HID*HID/4)
        int k = i >> 6;
        float4 w = ((const float4*)(Wres + HID * HID))[i];
        float gk = rmsw[HID + k];
        uint4 o4;
        o4.x = f2tf32(w.x * gk); o4.y = f2tf32(w.y * gk);
        o4.z = f2tf32(w.z * gk); o4.w = f2tf32(w.w * gk);
        ((uint4*)g_Wt)[i] = o4;
    }
}

// ---------------- bucket fill (counters pre-zeroed by memset) ----------------
__global__ void k_fill(const float* __restrict__ ef, const int* __restrict__ tri) {
    int i = blockIdx.x * 128 + threadIdx.x;   // 64 x 128 = 8192
    if (i >= N) return;
    float x0 = ef[3 * i], x1 = ef[3 * i + 1], x2 = ef[3 * i + 2];
    int t = tri[i];
    int slot = atomicAdd(&g_cntsum[t], 1);
    if (slot < CAP)
        g_tri_feat[t * CAP + slot] = make_float4(x0, x1, x2, 0.f);
}

// ---- fused attention + h1-build + tf32 resblock2 GEMM + exp + edge-sum ------
__global__ void __launch_bounds__(256, 1)
k_gemm(const float* __restrict__ ef, const int* __restrict__ tri,
       const int* __restrict__ eid,
       const float* __restrict__ b0, const float* __restrict__ b1,
       const float* __restrict__ b2, const float* __restrict__ Wout,
       const float* __restrict__ bout) {
    extern __shared__ float sm[];
    float* sH = sm;                                    // [BM][HSTR] h1 fp32
    uint32_t* sB = (uint32_t*)(sm + BM * HSTR);        // [32][BSTR] tf32
    float* sWout = (float*)(sB + 32 * BSTR);           // [HID]
    float* sBres = sWout + HID;                        // [HID]
    float* sRS = sBres + HID;                          // [BM]
    float* sRed = sRS + BM;                            // [BM*4]
    float4* sYa = (float4*)(sRed + BM * 4);            // [BM]

    int tid = threadIdx.x, lane = tid & 31, wid = tid >> 5;
    int row0 = blockIdx.x * BM;

    if (tid < HID) { sWout[tid] = Wout[tid]; sBres[tid] = b2[tid]; }

    // ---------- preload B tile kk=0 (ALL threads; hides attention latency) ---
#pragma unroll
    for (int it = 0; it < 8; it++) {
        int i = tid + it * 256;
        int k = i >> 6, c4 = i & 63;
        uint4 w = ((const uint4*)(g_Wt + k * HID))[c4];
        uint32_t* d = &sB[k * BSTR + c4 * 4];
        d[0] = w.x; d[1] = w.y; d[2] = w.z; d[3] = w.w;
    }

    // ---------- attention for this block's 64 nodes (tid < 64) ----------
    if (tid < BM) {
        int node = row0 + tid;
        float x0 = ef[3 * node], x1 = ef[3 * node + 1], x2 = ef[3 * node + 2];
        float u0 = x0 * g_M[0] + x1 * g_M[4] + x2 * g_M[8]  + g_M[12];
        float u1 = x0 * g_M[1] + x1 * g_M[5] + x2 * g_M[9]  + g_M[13];
        float u2 = x0 * g_M[2] + x1 * g_M[6] + x2 * g_M[10] + g_M[14];
        float u3 = x0 * g_M[3] + x1 * g_M[7] + x2 * g_M[11] + g_M[15];
        int t = tri[node];
        int cnt = g_cntsum[t];
        if (cnt > CAP) cnt = CAP;
        const float4* base = g_tri_feat + t * CAP;
        float sum = 0.f, y0 = 0.f, y1 = 0.f, y2 = 0.f;
#pragma unroll 4
        for (int j = 0; j < cnt; j++) {
            float4 f = base[j];
            float s = fmaf(u0, f.x, fmaf(u1, f.y, fmaf(u2, f.z, u3)));
            float w = __expf(s);     // |s| << 1: no max-shift needed
            sum += w;
            y0 = fmaf(w, f.x, y0); y1 = fmaf(w, f.y, y1); y2 = fmaf(w, f.z, y2);
        }
        float inv = 1.f / sum;
        sYa[tid] = make_float4(y0 * inv, y1 * inv, y2 * inv, 1.f);
    }
    __syncthreads();

    // ---------- prologue: each warp builds 8 rows of h1 ----------
    {
        int rbase = wid * 8;
        float4 ya[8];
#pragma unroll
        for (int m = 0; m < 8; m++) ya[m] = sYa[rbase + m];
        float sqr[8];
#pragma unroll
        for (int m = 0; m < 8; m++) sqr[m] = 0.f;
#pragma unroll
        for (int t = 0; t < 8; t++) {
            int c = lane + 32 * t;
            float C0 = g_C[c], C1 = g_C[256 + c], C2 = g_C[512 + c], C3 = g_C[768 + c];
            float bb = b0[c];
#pragma unroll
            for (int m = 0; m < 8; m++) {
                float v = bb;
                v = fmaf(ya[m].x, C0, v); v = fmaf(ya[m].y, C1, v);
                v = fmaf(ya[m].z, C2, v); v = fmaf(ya[m].w, C3, v);
                sH[(rbase + m) * HSTR + c] = v;
                sqr[m] = fmaf(v, v, sqr[m]);
            }
        }
        float rsr[8];
#pragma unroll
        for (int m = 0; m < 8; m++) {
            float s = sqr[m];
#pragma unroll
            for (int o = 16; o; o >>= 1) s += __shfl_xor_sync(0xffffffffu, s, o);
            rsr[m] = rsqrtf(s * (1.0f / 256.0f) + EPSF);
        }
        float sq2[8];
#pragma unroll
        for (int m = 0; m < 8; m++) sq2[m] = 0.f;
#pragma unroll
        for (int t = 0; t < 8; t++) {
            int c = lane + 32 * t;
            float D0 = g_D[c], D1 = g_D[256 + c], D2 = g_D[512 + c], D3 = g_D[768 + c];
            float D4 = g_D[1024 + c];
            float b1c = b1[c];
#pragma unroll
            for (int m = 0; m < 8; m++) {
                float z = D4;
                z = fmaf(ya[m].x, D0, z); z = fmaf(ya[m].y, D1, z);
                z = fmaf(ya[m].z, D2, z); z = fmaf(ya[m].w, D3, z);
                z = fmaf(rsr[m], z, b1c);
                float h0v = sH[(rbase + m) * HSTR + c];
                float h1v = h0v + fmaxf(z, 0.f);
                sH[(rbase + m) * HSTR + c] = h1v;
                sq2[m] = fmaf(h1v, h1v, sq2[m]);
            }
        }
#pragma unroll
        for (int m = 0; m < 8; m++) {
            float s = sq2[m];
#pragma unroll
            for (int o = 16; o; o >>= 1) s += __shfl_xor_sync(0xffffffffu, s, o);
            if (lane == 0) sRS[rbase + m] = rsqrtf(s * (1.0f / 256.0f) + EPSF);
        }
    }
    __syncthreads();

    // ---------- tf32 mma mainloop (tile kk=0 already in sB) ----------
    int wm = wid >> 2, wn = wid & 3;
    int lg = lane >> 2, lq = lane & 3;
    float rsv[4];
#pragma unroll
    for (int q = 0; q < 4; q++) rsv[q] = sRS[wm * 32 + q * 8 + lg];

    float acc[2][8][4];
#pragma unroll
    for (int mt = 0; mt < 2; mt++)
#pragma unroll
        for (int nt = 0; nt < 8; nt++)
#pragma unroll
            for (int q = 0; q < 4; q++) acc[mt][nt][q] = 0.f;

    for (int kk = 0; kk < HID; kk += 32) {
#pragma unroll
        for (int ks = 0; ks < 4; ks++) {
            int col = kk + ks * 8 + lq;
            uint32_t a[2][4];
#pragma unroll
            for (int mt = 0; mt < 2; mt++) {
                int r = wm * 32 + mt * 16 + lg;
                a[mt][0] = f2tf32(sH[r * HSTR + col] * rsv[mt * 2]);
                a[mt][1] = f2tf32(sH[(r + 8) * HSTR + col] * rsv[mt * 2 + 1]);
                a[mt][2] = f2tf32(sH[r * HSTR + col + 4] * rsv[mt * 2]);
                a[mt][3] = f2tf32(sH[(r + 8) * HSTR + col + 4] * rsv[mt * 2 + 1]);
            }
            int k0 = ks * 8;
            uint32_t b[8][2];
#pragma unroll
            for (int nt = 0; nt < 8; nt++) {
                int c = wn * 64 + nt * 8 + lg;
                b[nt][0] = sB[(k0 + lq) * BSTR + c];
                b[nt][1] = sB[(k0 + lq + 4) * BSTR + c];
            }
#pragma unroll
            for (int mt = 0; mt < 2; mt++)
#pragma unroll
                for (int nt = 0; nt < 8; nt++) {
                    asm volatile(
                        "mma.sync.aligned.m16n8k8.row.col.f32.tf32.tf32.f32 "
                        "{%0,%1,%2,%3}, {%4,%5,%6,%7}, {%8,%9}, {%0,%1,%2,%3};"
                        : "+f"(acc[mt][nt][0]), "+f"(acc[mt][nt][1]),
                          "+f"(acc[mt][nt][2]), "+f"(acc[mt][nt][3])
                        : "r"(a[mt][0]), "r"(a[mt][1]), "r"(a[mt][2]), "r"(a[mt][3]),
                          "r"(b[nt][0]), "r"(b[nt][1]));
                }
        }
        __syncthreads();
        if (kk + 32 < HID) {
            int kn = kk + 32;
#pragma unroll
            for (int it = 0; it < 8; it++) {
                int i = tid + it * 256;
                int k = i >> 6, c4 = i & 63;
                uint4 w = ((const uint4*)(g_Wt + (kn + k) * HID))[c4];
                uint32_t* d = &sB[k * BSTR + c4 * 4];
                d[0] = w.x; d[1] = w.y; d[2] = w.z; d[3] = w.w;
            }
            __syncthreads();
        }
    }

    // ---------- epilogue: residual + relu + Wout dot ----------
#pragma unroll
    for (int mt = 0; mt < 2; mt++) {
        int i0 = wm * 32 + mt * 16 + lg;
        int i1 = i0 + 8;
        float plo = 0.f, phi = 0.f;
#pragma unroll
        for (int nt = 0; nt < 8; nt++) {
            int j0 = wn * 64 + nt * 8 + lq * 2;
            float w0 = sWout[j0], w1 = sWout[j0 + 1];
            float br0 = sBres[j0], br1 = sBres[j0 + 1];
            float h00 = sH[i0 * HSTR + j0], h01 = sH[i0 * HSTR + j0 + 1];
            float h10 = sH[i1 * HSTR + j0], h11 = sH[i1 * HSTR + j0 + 1];
            plo = fmaf(h00 + fmaxf(acc[mt][nt][0] + br0, 0.f), w0, plo);
            plo = fmaf(h01 + fmaxf(acc[mt][nt][1] + br1, 0.f), w1, plo);
            phi = fmaf(h10 + fmaxf(acc[mt][nt][2] + br0, 0.f), w0, phi);
            phi = fmaf(h11 + fmaxf(acc[mt][nt][3] + br1, 0.f), w1, phi);
        }
        plo += __shfl_xor_sync(0xffffffffu, plo, 1);
        plo += __shfl_xor_sync(0xffffffffu, plo, 2);
        phi += __shfl_xor_sync(0xffffffffu, phi, 1);
        phi += __shfl_xor_sync(0xffffffffu, phi, 2);
        if (lq == 0) {
            sRed[i0 * 4 + wn] = plo;
            sRed[i1 * 4 + wn] = phi;
        }
    }
    __syncthreads();
    // logits are tiny (|l| << 1): exp without max-shift is safe.
    if (tid < BM) {
        float v = sRed[tid * 4] + sRed[tid * 4 + 1] + sRed[tid * 4 + 2] + sRed[tid * 4 + 3];
        float ev = __expf(v + bout[0]);
        int node = row0 + tid;
        g_eexp[node] = ev;
        float* esum = (float*)(g_cntsum + NTRI);
        atomicAdd(&esum[eid[node]], ev);
    }
}

// ---------------- normalize ---------------------------------------------------
__global__ void k_norm(const int* __restrict__ eid, float* __restrict__ out) {
    int i = blockIdx.x * 256 + threadIdx.x;
    if (i >= N) return;
    const float* esum = (const float*)(g_cntsum + NTRI);
    out[i] = g_eexp[i] / esum[eid[i]];
}

// ---------------- launcher ---------------------------------------------------
extern "C" void kernel_launch(void* const* d_in, const int* in_sizes, int n_in,
                              void* d_out, int out_size) {
    const float* ef   = (const float*)d_in[0];
    const int*   eid  = (const int*)d_in[1];
    const int*   tri  = (const int*)d_in[2];
    const float* Wq   = (const float*)d_in[3];
    const float* bq   = (const float*)d_in[4];
    const float* Wk   = (const float*)d_in[5];
    const float* bk   = (const float*)d_in[6];
    const float* Wv   = (const float*)d_in[7];
    const float* bv   = (const float*)d_in[8];
    const float* W0   = (const float*)d_in[9];
    const float* b0   = (const float*)d_in[10];
    const float* rmsw = (const float*)d_in[11];
    const float* Wres = (const float*)d_in[12];
    const float* bres = (const float*)d_in[13];
    const float* Wout = (const float*)d_in[14];
    const float* bout = (const float*)d_in[15];
    float* out = (float*)d_out;

    const size_t smem = (BM * HSTR + 32 * BSTR + 2 * HID + BM + BM * 4 + BM * 4) * sizeof(float);

    // lazy one-time setup (runs on the uncaptured correctness call)
    static cudaStream_t s2 = nullptr;
    static cudaEvent_t eFork = nullptr, eInit = nullptr;
    static void* p_zero = nullptr;
    if (!p_zero) {
        cudaStreamCreateWithFlags(&s2, cudaStreamNonBlocking);
        cudaEventCreateWithFlags(&eFork, cudaEventDisableTiming);
        cudaEventCreateWithFlags(&eInit, cudaEventDisableTiming);
        cudaGetSymbolAddress(&p_zero, g_cntsum);
        cudaFuncSetAttribute(k_gemm, cudaFuncAttributeMaxDynamicSharedMemorySize, (int)smem);
    }

    // fork side stream off the main (capture) stream
    cudaEventRecord(eFork, 0);
    cudaStreamWaitEvent(s2, eFork, 0);

    // side stream: weight preprocessing (wide, short)
    k_initMC<<<1, 1024, 0, s2>>>(Wq, bq, Wk, bk, Wv, bv, W0);
    k_initDW<<<69, 256, 0, s2>>>(rmsw, Wres, b0);
    cudaEventRecord(eInit, s2);

    // main stream: memset -> fill -> gemm -> norm
    cudaMemsetAsync(p_zero, 0, (NTRI + NEDGE) * sizeof(int), 0);
    k_fill<<<64, 128>>>(ef, tri);
    cudaStreamWaitEvent(0, eInit, 0);         // gemm needs g_M, g_C, g_D, g_Wt
    k_gemm<<<N / BM, 256, smem>>>(ef, tri, eid, b0, bres, bres + HID, Wout, bout);
    k_norm<<<N / 256, 256>>>(eid, out);
}